// round 2
// baseline (speedup 1.0000x reference)
#include <cuda_runtime.h>
#include <cstdint>

// Global double accumulator for sum(1 - cos) — __device__ global, no allocation.
__device__ double g_acc;

__global__ void zero_acc_kernel() {
    g_acc = 0.0;
}

// One warp per row. Row length C=1000 floats = 250 float4 (row stride 4000B is
// 16B-aligned). Warp streams the row, reduces sum-of-squares via shuffles,
// lane 0 fetches logits[row, label] (hot in L1/L2) and forms (1 - cos).
__global__ __launch_bounds__(256)
void cosine_loss_kernel(const float* __restrict__ logits,
                        const int* __restrict__ labels,   // JAX default: int32
                        int N, int C) {
    const int gwarp = (blockIdx.x * blockDim.x + threadIdx.x) >> 5;
    const int lane  = threadIdx.x & 31;
    const int warp_in_block = threadIdx.x >> 5;

    double local = 0.0;

    if (gwarp < N) {
        const size_t row_off = (size_t)gwarp * (size_t)C;
        const float4* __restrict__ row4 = reinterpret_cast<const float4*>(logits + row_off);
        const int n4 = C >> 2;  // 250

        float s = 0.0f;
        // lanes 0..25 do 8 iters, lanes 26..31 do 7 — fully coalesced.
        for (int j = lane; j < n4; j += 32) {
            float4 v = __ldg(row4 + j);
            s = fmaf(v.x, v.x, s);
            s = fmaf(v.y, v.y, s);
            s = fmaf(v.z, v.z, s);
            s = fmaf(v.w, v.w, s);
        }
        // warp reduction of sum of squares
        #pragma unroll
        for (int o = 16; o > 0; o >>= 1)
            s += __shfl_xor_sync(0xFFFFFFFFu, s, o);

        if (lane == 0) {
            const int lab = labels[gwarp];
            const float dot = __ldg(logits + row_off + (size_t)lab);
            const float norm = sqrtf(s);
            const float cosv = dot / fmaxf(norm, 1e-8f);
            local = 1.0 - (double)cosv;
        }
    }

    // Block reduction of per-warp partials (8 warps/block), then one atomic.
    __shared__ double sh[8];
    if (lane == 0) sh[warp_in_block] = local;
    __syncthreads();
    if (threadIdx.x == 0) {
        double t = 0.0;
        #pragma unroll
        for (int i = 0; i < 8; i++) t += sh[i];
        atomicAdd(&g_acc, t);
    }
}

__global__ void finalize_kernel(float* __restrict__ out, double inv_n) {
    *out = (float)(g_acc * inv_n);
}

extern "C" void kernel_launch(void* const* d_in, const int* in_sizes, int n_in,
                              void* d_out, int out_size) {
    const float* logits = (const float*)d_in[0];
    const int*   labels = (const int*)d_in[1];
    float* out = (float*)d_out;

    const int N = in_sizes[1];              // number of rows == number of labels
    const int C = in_sizes[0] / N;          // 1000

    zero_acc_kernel<<<1, 1>>>();

    const int threads = 256;                       // 8 warps/block
    const int blocks = (N * 32 + threads - 1) / threads;
    cosine_loss_kernel<<<blocks, threads>>>(logits, labels, N, C);

    finalize_kernel<<<1, 1>>>(out, 1.0 / (double)N);
}